// round 8
// baseline (speedup 1.0000x reference)
#include <cuda_runtime.h>
#include <cuda_bf16.h>
#include <math.h>
#include <float.h>
#include <stdint.h>

// Gate_33827162423867 — single fused HMMA router kernel.
// score = x[16384,4096] @ W[64,4096]^T via bf16 2-split (hi/lo, 3 products,
// fp32 accum, mma.sync.m16n8k16) -> FTZ softmax -> top-8 of probs.
// Knife-edge tokens (tiny top-9 logit gaps or logits near FTZ flush
// boundaries) are recomputed exactly IN-CTA (serial fp32 FMA per 1024-slice,
// slices folded serially == cublas splitK4 order) and their outputs rewritten.
// Output: d_out float*, [0,T*8) gate weights, [T*8, 2*T*8) indices-as-float.

#define NE    64
#define TB    128
#define KCH   64
#define NT    256
#define TOPK  8

#define EPS_GAP 0.01f
#define EPS_B   0.01f
#define LN_FLT_MIN -87.33654475055310898657124730373f

#define RS    72      // bf16 tile row stride (elements); 144B rows, ldmatrix conflict-free
#define SSTR  65      // scores row stride (floats): bank-conflict-free per-token rows
#define FSTR  73      // fixup row stride (floats): conflict-free across parallel epilogues
#define MAXFLAG 32

// dynamic smem: two GEMM buffers of 55296 B each
#define BUFB  55296
#define SM_XH 0
#define SM_XL 18432
#define SM_WH 36864
#define SM_WL 46080
#define SM_FIX 65536          // fixup scores (aliases buf1; used after GEMM)
#define SMEM_DYN 110592

// ---------------- helpers ----------------
__device__ __forceinline__ uint32_t smem_u32(const void* p) {
    uint32_t a;
    asm("{ .reg .u64 t; cvta.to.shared.u64 t, %1; cvt.u32.u64 %0, t; }"
        : "=r"(a) : "l"(p));
    return a;
}
__device__ __forceinline__ uint32_t cvt_bf16x2(float lo, float hi) {
    uint32_t r;
    asm("cvt.rn.bf16x2.f32 %0, %1, %2;" : "=r"(r) : "f"(hi), "f"(lo));
    return r;
}
__device__ __forceinline__ float bflo_f(uint32_t h) { return __uint_as_float(h << 16); }
__device__ __forceinline__ float bfhi_f(uint32_t h) { return __uint_as_float(h & 0xFFFF0000u); }

__device__ __forceinline__ void ldm_x4(uint32_t addr, uint32_t& r0, uint32_t& r1,
                                       uint32_t& r2, uint32_t& r3) {
    asm volatile("ldmatrix.sync.aligned.m8n8.x4.shared.b16 {%0,%1,%2,%3}, [%4];"
                 : "=r"(r0), "=r"(r1), "=r"(r2), "=r"(r3) : "r"(addr));
}
__device__ __forceinline__ void mma_bf16(float* d, uint32_t a0, uint32_t a1,
                                         uint32_t a2, uint32_t a3,
                                         uint32_t b0, uint32_t b1) {
    asm volatile(
        "mma.sync.aligned.m16n8k16.row.col.f32.bf16.bf16.f32 "
        "{%0,%1,%2,%3}, {%4,%5,%6,%7}, {%8,%9}, {%0,%1,%2,%3};"
        : "+f"(d[0]), "+f"(d[1]), "+f"(d[2]), "+f"(d[3])
        : "r"(a0), "r"(a1), "r"(a2), "r"(a3), "r"(b0), "r"(b1));
}

// ================= single fused kernel =================
__global__ __launch_bounds__(NT, 1)
void gate_kernel(const float* __restrict__ x,
                 const float* __restrict__ w,
                 float* __restrict__ out,
                 int dim, int tokens)
{
    extern __shared__ char dyn[];
    __shared__ int   s_nflag;
    __shared__ int   s_flags[MAXFLAG];
    __shared__ float s_part[2][4 * NE];

    const uint32_t sbase = smem_u32(dyn);
    const int tid  = threadIdx.x;
    const int wid  = tid >> 5;
    const int lane = tid & 31;
    const int token0 = blockIdx.x * TB;

    if (tid == 0) s_nflag = 0;

    // convert mappings
    const int xrow  = tid >> 1;           // 0..127
    const int xcol0 = (tid & 1) * 32;     // 0 or 32
    const int wrow  = tid >> 2;           // 0..63
    const int wcol0 = (tid & 3) * 16;     // 0,16,32,48

    // ldmatrix per-lane byte offsets (constant across chunks)
    const int tokb = wid * 16;
    const uint32_t aoff = (uint32_t)((tokb + (lane & 7) + (((lane >> 3) & 1) * 8)) * (RS * 2)
                                     + ((lane >> 4) * 16));
    const uint32_t boff_base = (uint32_t)(((lane & 7) + ((lane >> 4) * 8)) * (RS * 2)
                                          + (((lane >> 3) & 1) * 16));

    float acc[8][4];
    #pragma unroll
    for (int n = 0; n < 8; n++)
        #pragma unroll
        for (int i = 0; i < 4; i++) acc[n][i] = 0.0f;

    const int nchunks = dim / KCH;        // 64

    float4 xr[8];
    float4 wr[4];
    {
        const float* xsrc = x + (size_t)(token0 + xrow) * dim + xcol0;
        #pragma unroll
        for (int i = 0; i < 4; i++) {
            xr[2 * i]     = *reinterpret_cast<const float4*>(xsrc + i * 8);
            xr[2 * i + 1] = *reinterpret_cast<const float4*>(xsrc + i * 8 + 4);
        }
        const float* wsrc = w + (size_t)wrow * dim + wcol0;
        #pragma unroll
        for (int i = 0; i < 2; i++) {
            wr[2 * i]     = *reinterpret_cast<const float4*>(wsrc + i * 8);
            wr[2 * i + 1] = *reinterpret_cast<const float4*>(wsrc + i * 8 + 4);
        }
    }

    for (int c = 0; c < nchunks; c++) {
        const uint32_t bufo = (uint32_t)((c & 1) * BUFB);
        // ---- convert + STS current chunk into buf[c&1] ----
        {
            char* xh = dyn + bufo + SM_XH;
            char* xl = dyn + bufo + SM_XL;
            #pragma unroll
            for (int i = 0; i < 4; i++) {
                float4 a = xr[2 * i], b = xr[2 * i + 1];
                uint32_t h0 = cvt_bf16x2(a.x, a.y);
                uint32_t h1 = cvt_bf16x2(a.z, a.w);
                uint32_t h2 = cvt_bf16x2(b.x, b.y);
                uint32_t h3 = cvt_bf16x2(b.z, b.w);
                uint32_t l0 = cvt_bf16x2(a.x - bflo_f(h0), a.y - bfhi_f(h0));
                uint32_t l1 = cvt_bf16x2(a.z - bflo_f(h1), a.w - bfhi_f(h1));
                uint32_t l2 = cvt_bf16x2(b.x - bflo_f(h2), b.y - bfhi_f(h2));
                uint32_t l3 = cvt_bf16x2(b.z - bflo_f(h3), b.w - bfhi_f(h3));
                uint32_t off = (uint32_t)(xrow * (RS * 2) + (xcol0 + i * 8) * 2);
                *reinterpret_cast<uint4*>(xh + off) = make_uint4(h0, h1, h2, h3);
                *reinterpret_cast<uint4*>(xl + off) = make_uint4(l0, l1, l2, l3);
            }
            char* wh = dyn + bufo + SM_WH;
            char* wl = dyn + bufo + SM_WL;
            #pragma unroll
            for (int i = 0; i < 2; i++) {
                float4 a = wr[2 * i], b = wr[2 * i + 1];
                uint32_t h0 = cvt_bf16x2(a.x, a.y);
                uint32_t h1 = cvt_bf16x2(a.z, a.w);
                uint32_t h2 = cvt_bf16x2(b.x, b.y);
                uint32_t h3 = cvt_bf16x2(b.z, b.w);
                uint32_t l0 = cvt_bf16x2(a.x - bflo_f(h0), a.y - bfhi_f(h0));
                uint32_t l1 = cvt_bf16x2(a.z - bflo_f(h1), a.w - bfhi_f(h1));
                uint32_t l2 = cvt_bf16x2(b.x - bflo_f(h2), b.y - bfhi_f(h2));
                uint32_t l3 = cvt_bf16x2(b.z - bflo_f(h3), b.w - bfhi_f(h3));
                uint32_t off = (uint32_t)(wrow * (RS * 2) + (wcol0 + i * 8) * 2);
                *reinterpret_cast<uint4*>(wh + off) = make_uint4(h0, h1, h2, h3);
                *reinterpret_cast<uint4*>(wl + off) = make_uint4(l0, l1, l2, l3);
            }
        }
        // ---- preload next chunk (hides behind this chunk's MMA) ----
        if (c + 1 < nchunks) {
            const int k0n = (c + 1) * KCH;
            const float* xsrc = x + (size_t)(token0 + xrow) * dim + k0n + xcol0;
            #pragma unroll
            for (int i = 0; i < 4; i++) {
                xr[2 * i]     = *reinterpret_cast<const float4*>(xsrc + i * 8);
                xr[2 * i + 1] = *reinterpret_cast<const float4*>(xsrc + i * 8 + 4);
            }
            const float* wsrc = w + (size_t)wrow * dim + k0n + wcol0;
            #pragma unroll
            for (int i = 0; i < 2; i++) {
                wr[2 * i]     = *reinterpret_cast<const float4*>(wsrc + i * 8);
                wr[2 * i + 1] = *reinterpret_cast<const float4*>(wsrc + i * 8 + 4);
            }
        }
        __syncthreads();   // buf[c&1] fully written; prev readers of it are done

        // ---- MMA phase: 4 k-steps x 4 expert-pairs x 3 products ----
        #pragma unroll
        for (int ks = 0; ks < 4; ks++) {
            const uint32_t kb = (uint32_t)(ks * 32);
            uint32_t ah0, ah1, ah2, ah3, al0, al1, al2, al3;
            ldm_x4(sbase + bufo + SM_XH + aoff + kb, ah0, ah1, ah2, ah3);
            ldm_x4(sbase + bufo + SM_XL + aoff + kb, al0, al1, al2, al3);
            #pragma unroll
            for (int p = 0; p < 4; p++) {
                const uint32_t bo = boff_base + (uint32_t)(p * 16 * (RS * 2)) + kb;
                uint32_t bh0, bh1, bh2, bh3, bl0, bl1, bl2, bl3;
                ldm_x4(sbase + bufo + SM_WH + bo, bh0, bh1, bh2, bh3);
                ldm_x4(sbase + bufo + SM_WL + bo, bl0, bl1, bl2, bl3);
                mma_bf16(acc[2 * p], ah0, ah1, ah2, ah3, bh0, bh1);
                mma_bf16(acc[2 * p], ah0, ah1, ah2, ah3, bl0, bl1);
                mma_bf16(acc[2 * p], al0, al1, al2, al3, bh0, bh1);
                mma_bf16(acc[2 * p + 1], ah0, ah1, ah2, ah3, bh2, bh3);
                mma_bf16(acc[2 * p + 1], ah0, ah1, ah2, ah3, bl2, bl3);
                mma_bf16(acc[2 * p + 1], al0, al1, al2, al3, bh2, bh3);
            }
        }
    }

    // ---- write accumulators to padded smem scores [128][SSTR] ----
    float* scores = reinterpret_cast<float*>(dyn);
    {
        const int g  = lane >> 2;         // 0..7
        const int t2 = (lane & 3) * 2;    // 0,2,4,6
        #pragma unroll
        for (int n = 0; n < 8; n++) {
            const int col = n * 8 + t2;
            scores[(tokb + g) * SSTR + col]         = acc[n][0];
            scores[(tokb + g) * SSTR + col + 1]     = acc[n][1];
            scores[(tokb + g + 8) * SSTR + col]     = acc[n][2];
            scores[(tokb + g + 8) * SSTR + col + 1] = acc[n][3];
        }
    }
    __syncthreads();

    // ---- fast epilogue: 1 thread per token, all state in smem ----
    if (tid < TB) {
        float* srow = scores + tid * SSTR;
        float m = -FLT_MAX;
        #pragma unroll
        for (int e = 0; e < NE; e++) m = fmaxf(m, srow[e]);

        float denom = 0.0f;
        #pragma unroll
        for (int e = 0; e < NE; e++) {
            float q = __expf(srow[e] - m);
            if (q < FLT_MIN) q = 0.0f;
            denom += q;
        }

        // knife-edge flag (on logits, before overwrite)
        bool flag = false;
        float b2 = LN_FLT_MIN + __logf(denom);
        #pragma unroll
        for (int e = 0; e < NE; e++) {
            float d = srow[e] - m;
            if (fabsf(d - LN_FLT_MIN) < EPS_B || fabsf(d - b2) < EPS_B) flag = true;
        }
        {
            unsigned long long used = 0ull;
            float prevv = 0.0f;
            for (int j = 0; j < 9; j++) {
                float best = -FLT_MAX; int bi = 0;
                for (int e = 0; e < NE; e++)
                    if (!((used >> e) & 1ull) && srow[e] > best) { best = srow[e]; bi = e; }
                used |= 1ull << bi;
                if (j > 0 && (prevv - best) < EPS_GAP) flag = true;
                prevv = best;
            }
        }

        // probs in place (FTZ at exp and after normalize)
        float inv = 1.0f / denom;
        #pragma unroll
        for (int e = 0; e < NE; e++) {
            float q = __expf(srow[e] - m);
            if (q < FLT_MIN) q = 0.0f;
            q *= inv;
            if (q < FLT_MIN) q = 0.0f;
            srow[e] = q;
        }

        const int tglob = token0 + tid;
        float* out_w   = out + (size_t)tglob * TOPK;
        float* out_idx = out + (size_t)tokens * TOPK + (size_t)tglob * TOPK;
        #pragma unroll
        for (int j = 0; j < TOPK; j++) {
            float best = -1.0f; int bi = 0;
            for (int e = 0; e < NE; e++)
                if (srow[e] > best) { best = srow[e]; bi = e; }  // lowest idx wins ties
            srow[bi] = -1.0f;
            out_w[j]   = best;
            out_idx[j] = (float)bi;
        }

        if (flag) {
            int i = atomicAdd(&s_nflag, 1);
            if (i < MAXFLAG) s_flags[i] = tid;
        }
    }
    __syncthreads();

    // ---- in-CTA exact fixup ----
    const int nf = (s_nflag < MAXFLAG) ? s_nflag : MAXFLAG;
    if (nf > 0) {
        const int e  = tid & 63;
        const int sl = tid >> 6;            // slice 0..3
        const int slice = dim >> 2;         // 1024
        float* fixb = reinterpret_cast<float*>(dyn + SM_FIX);

        // phase A: exact scores for flagged tokens, 2 at a time
        for (int f0 = 0; f0 < nf; f0 += 2) {
            const int f1 = (f0 + 1 < nf) ? f0 + 1 : f0;
            const float* xr0 = x + (size_t)(token0 + s_flags[f0]) * dim + sl * slice;
            const float* xr1 = x + (size_t)(token0 + s_flags[f1]) * dim + sl * slice;
            const float* wrp = w + (size_t)e * dim + sl * slice;
            float a0 = 0.0f, a1 = 0.0f;
            for (int k = 0; k < slice; k += 4) {   // serial ascending-k fp32 chain
                float4 wv = *reinterpret_cast<const float4*>(wrp + k);
                float4 v0 = *reinterpret_cast<const float4*>(xr0 + k);
                float4 v1 = *reinterpret_cast<const float4*>(xr1 + k);
                a0 = fmaf(v0.x, wv.x, a0); a1 = fmaf(v1.x, wv.x, a1);
                a0 = fmaf(v0.y, wv.y, a0); a1 = fmaf(v1.y, wv.y, a1);
                a0 = fmaf(v0.z, wv.z, a0); a1 = fmaf(v1.z, wv.z, a1);
                a0 = fmaf(v0.w, wv.w, a0); a1 = fmaf(v1.w, wv.w, a1);
            }
            s_part[0][e * 4 + sl] = a0;
            s_part[1][e * 4 + sl] = a1;
            __syncthreads();
            if (tid < NE) {
                float t0 = ((s_part[0][tid * 4] + s_part[0][tid * 4 + 1])
                            + s_part[0][tid * 4 + 2]) + s_part[0][tid * 4 + 3];
                float t1 = ((s_part[1][tid * 4] + s_part[1][tid * 4 + 1])
                            + s_part[1][tid * 4 + 2]) + s_part[1][tid * 4 + 3];
                fixb[f0 * FSTR + tid] = t0;
                fixb[f1 * FSTR + tid] = t1;
            }
            __syncthreads();
        }

        // phase B: exact epilogue per flagged token (parallel, ≤32 threads)
        if (tid < nf) {
            float* srow = fixb + tid * FSTR;
            float m = -FLT_MAX;
            for (int ee = 0; ee < NE; ee++) m = fmaxf(m, srow[ee]);
            float denom = 0.0f;
            for (int ee = 0; ee < NE; ee++) {
                float q = expf(srow[ee] - m);      // exact libdevice exp
                if (q < FLT_MIN) q = 0.0f;
                srow[ee] = q;
                denom += q;
            }
            float inv = 1.0f / denom;
            for (int ee = 0; ee < NE; ee++) {
                float q = srow[ee] * inv;
                if (q < FLT_MIN) q = 0.0f;
                srow[ee] = q;
            }
            const int tglob = token0 + s_flags[tid];
            float* out_w   = out + (size_t)tglob * TOPK;
            float* out_idx = out + (size_t)tokens * TOPK + (size_t)tglob * TOPK;
            for (int j = 0; j < TOPK; j++) {
                float best = -1.0f; int bi = 0;
                for (int ee = 0; ee < NE; ee++)
                    if (srow[ee] > best) { best = srow[ee]; bi = ee; }
                srow[bi] = -1.0f;
                out_w[j]   = best;
                out_idx[j] = (float)bi;
            }
        }
    }
}

// ================= launch =================
extern "C" void kernel_launch(void* const* d_in, const int* in_sizes, int n_in,
                              void* d_out, int out_size)
{
    const float* x = (const float*)d_in[0];
    const float* w = (const float*)d_in[1];
    // d_in[2] = bias: dead code in the reference

    const int num_experts = in_sizes[2];                 // 64
    const int dim         = in_sizes[1] / num_experts;   // 4096
    const int tokens      = in_sizes[0] / dim;           // 16384
    float* out = (float*)d_out;

    // idempotent, called every time (no static guards allowed)
    cudaFuncSetAttribute(gate_kernel,
                         cudaFuncAttributeMaxDynamicSharedMemorySize, SMEM_DYN);

    gate_kernel<<<tokens / TB, NT, SMEM_DYN>>>(x, w, out, dim, tokens);
}

// round 9
// speedup vs baseline: 1.0684x; 1.0684x over previous
#include <cuda_runtime.h>
#include <cuda_bf16.h>
#include <math.h>
#include <float.h>
#include <stdint.h>

// Gate_33827162423867 — fused HMMA router, cp.async-pipelined.
// score = x[16384,4096] @ W[64,4096]^T via bf16 2-split (hi/lo, 3 products,
// fp32 accum, mma.sync.m16n8k16) -> FTZ softmax -> top-8 of probs.
// Raw fp32 tiles stream through a 3-stage cp.async smem ring (high MLP);
// convert reads smem, not gmem-bound registers. Knife-edge tokens are
// recomputed exactly in-CTA (serial fp32 FMA per 1024-slice, slices folded
// serially == cublas splitK4 order) and their outputs rewritten.
// Output: d_out float*, [0,T*8) gate weights, [T*8, 2*T*8) indices-as-float.

#define NE    64
#define TB    128
#define KCH   64
#define NT    256
#define TOPK  8

#define EPS_GAP 0.01f
#define EPS_B   0.01f
#define LN_FLT_MIN -87.33654475055310898657124730373f

#define RS    72      // bf16 tile row stride (elements); 144B rows
#define SSTR  65      // scores row stride (floats)
#define FSTR  73      // fixup row stride (floats)
#define MAXFLAG 32

// raw fp32 staging (floats): x rows stride 72 (288B), w rows stride 80 (320B)
#define XSTRF 72
#define WSTRF 80
#define XRAW_BYTES (TB * XSTRF * 4)        // 36864
#define WRAW_BYTES (NE * WSTRF * 4)        // 20480
#define STAGE_BYTES (XRAW_BYTES + WRAW_BYTES)   // 57344
#define NSTAGE 3
#define RAW_TOTAL (NSTAGE * STAGE_BYTES)   // 172032

// bf16 tiles (single buffer) after the raw ring
#define SM_XH (RAW_TOTAL + 0)
#define SM_XL (RAW_TOTAL + 18432)
#define SM_WH (RAW_TOTAL + 36864)
#define SM_WL (RAW_TOTAL + 46080)
#define SMEM_DYN (RAW_TOTAL + 55296)       // 227328

#define SM_FIX 65536   // fixup scores: aliases raw ring (GEMM finished by then)

// ---------------- helpers ----------------
__device__ __forceinline__ uint32_t smem_u32(const void* p) {
    uint32_t a;
    asm("{ .reg .u64 t; cvta.to.shared.u64 t, %1; cvt.u32.u64 %0, t; }"
        : "=r"(a) : "l"(p));
    return a;
}
__device__ __forceinline__ uint32_t cvt_bf16x2(float lo, float hi) {
    uint32_t r;
    asm("cvt.rn.bf16x2.f32 %0, %1, %2;" : "=r"(r) : "f"(hi), "f"(lo));
    return r;
}
__device__ __forceinline__ float bflo_f(uint32_t h) { return __uint_as_float(h << 16); }
__device__ __forceinline__ float bfhi_f(uint32_t h) { return __uint_as_float(h & 0xFFFF0000u); }

__device__ __forceinline__ void cp16(uint32_t smem_addr, const void* gptr) {
    asm volatile("cp.async.cg.shared.global [%0], [%1], 16;"
                 :: "r"(smem_addr), "l"(gptr));
}
__device__ __forceinline__ void cp_commit() {
    asm volatile("cp.async.commit_group;" ::: "memory");
}
__device__ __forceinline__ void cp_wait2() {
    asm volatile("cp.async.wait_group 2;" ::: "memory");
}

__device__ __forceinline__ void ldm_x4(uint32_t addr, uint32_t& r0, uint32_t& r1,
                                       uint32_t& r2, uint32_t& r3) {
    asm volatile("ldmatrix.sync.aligned.m8n8.x4.shared.b16 {%0,%1,%2,%3}, [%4];"
                 : "=r"(r0), "=r"(r1), "=r"(r2), "=r"(r3) : "r"(addr));
}
__device__ __forceinline__ void mma_bf16(float* d, uint32_t a0, uint32_t a1,
                                         uint32_t a2, uint32_t a3,
                                         uint32_t b0, uint32_t b1) {
    asm volatile(
        "mma.sync.aligned.m16n8k16.row.col.f32.bf16.bf16.f32 "
        "{%0,%1,%2,%3}, {%4,%5,%6,%7}, {%8,%9}, {%0,%1,%2,%3};"
        : "+f"(d[0]), "+f"(d[1]), "+f"(d[2]), "+f"(d[3])
        : "r"(a0), "r"(a1), "r"(a2), "r"(a3), "r"(b0), "r"(b1));
}

// ================= single fused kernel =================
__global__ __launch_bounds__(NT, 1)
void gate_kernel(const float* __restrict__ x,
                 const float* __restrict__ w,
                 float* __restrict__ out,
                 int dim, int tokens)
{
    extern __shared__ char dyn[];
    __shared__ int   s_nflag;
    __shared__ int   s_flags[MAXFLAG];
    __shared__ float s_part[2][4 * NE];

    const uint32_t sbase = smem_u32(dyn);
    const int tid  = threadIdx.x;
    const int wid  = tid >> 5;
    const int lane = tid & 31;
    const int token0 = blockIdx.x * TB;

    if (tid == 0) s_nflag = 0;

    const int nchunks = dim / KCH;        // 64

    // ---- cp.async issue helper (per-thread slices) ----
    // x: 2048 16B ops -> 8/thread ; w: 1024 ops -> 4/thread
    auto issue_chunk = [&](int c) {
        const uint32_t so = (uint32_t)((c % NSTAGE) * STAGE_BYTES);
        const int k0 = c * KCH;
        #pragma unroll
        for (int i = 0; i < 8; i++) {
            int o   = tid + i * NT;            // 0..2047
            int row = o >> 4;
            int seg = o & 15;
            uint32_t dst = sbase + so + (uint32_t)(row * (XSTRF * 4) + seg * 16);
            const float* src = x + (size_t)(token0 + row) * dim + k0 + seg * 4;
            cp16(dst, src);
        }
        #pragma unroll
        for (int i = 0; i < 4; i++) {
            int o   = tid + i * NT;            // 0..1023
            int row = o >> 4;
            int seg = o & 15;
            uint32_t dst = sbase + so + (uint32_t)(XRAW_BYTES + row * (WSTRF * 4) + seg * 16);
            const float* src = w + (size_t)row * dim + k0 + seg * 4;
            cp16(dst, src);
        }
    };

    // prologue: 3 stages in flight
    issue_chunk(0); cp_commit();
    issue_chunk(1); cp_commit();
    issue_chunk(2); cp_commit();

    // convert mappings
    const int xrow = tid >> 1;            // 0..127
    const int xc0  = (tid & 1) * 4;       // 0 or 4 (8-stride interleave)
    const int wrow = tid >> 2;            // 0..63
    const int wc0  = (tid & 3) * 4;       // 0,4,8,12 (16-stride interleave)

    // ldmatrix per-lane byte offsets
    const int tokb = wid * 16;
    const uint32_t aoff = (uint32_t)((tokb + (lane & 7) + (((lane >> 3) & 1) * 8)) * (RS * 2)
                                     + ((lane >> 4) * 16));
    const uint32_t boff_base = (uint32_t)(((lane & 7) + ((lane >> 4) * 8)) * (RS * 2)
                                          + (((lane >> 3) & 1) * 16));

    float acc[8][4];
    #pragma unroll
    for (int n = 0; n < 8; n++)
        #pragma unroll
        for (int i = 0; i < 4; i++) acc[n][i] = 0.0f;

    for (int c = 0; c < nchunks; c++) {
        const uint32_t so = (uint32_t)((c % NSTAGE) * STAGE_BYTES);

        cp_wait2();            // chunk c's group complete
        __syncthreads();       // raw visible to all; prev MMA done (bf16 free)

        // ---- convert raw fp32 (smem) -> bf16 hi/lo tiles ----
        {
            const float* xraw = reinterpret_cast<const float*>(dyn + so);
            char* xh = dyn + SM_XH;
            char* xl = dyn + SM_XL;
            #pragma unroll
            for (int j = 0; j < 8; j++) {
                const int col = xc0 + j * 8;
                float4 a = *reinterpret_cast<const float4*>(xraw + xrow * XSTRF + col);
                uint32_t h0 = cvt_bf16x2(a.x, a.y);
                uint32_t h1 = cvt_bf16x2(a.z, a.w);
                uint32_t l0 = cvt_bf16x2(a.x - bflo_f(h0), a.y - bfhi_f(h0));
                uint32_t l1 = cvt_bf16x2(a.z - bflo_f(h1), a.w - bfhi_f(h1));
                uint32_t off = (uint32_t)(xrow * (RS * 2) + col * 2);
                *reinterpret_cast<uint2*>(xh + off) = make_uint2(h0, h1);
                *reinterpret_cast<uint2*>(xl + off) = make_uint2(l0, l1);
            }
            const float* wraw = reinterpret_cast<const float*>(dyn + so + XRAW_BYTES);
            char* wh = dyn + SM_WH;
            char* wl = dyn + SM_WL;
            #pragma unroll
            for (int j = 0; j < 4; j++) {
                const int col = wc0 + j * 16;
                float4 a = *reinterpret_cast<const float4*>(wraw + wrow * WSTRF + col);
                uint32_t h0 = cvt_bf16x2(a.x, a.y);
                uint32_t h1 = cvt_bf16x2(a.z, a.w);
                uint32_t l0 = cvt_bf16x2(a.x - bflo_f(h0), a.y - bfhi_f(h0));
                uint32_t l1 = cvt_bf16x2(a.z - bflo_f(h1), a.w - bfhi_f(h1));
                uint32_t off = (uint32_t)(wrow * (RS * 2) + col * 2);
                *reinterpret_cast<uint2*>(wh + off) = make_uint2(h0, h1);
                *reinterpret_cast<uint2*>(wl + off) = make_uint2(l0, l1);
            }
        }
        __syncthreads();       // bf16 ready; raw stage free for refill

        // refill this stage with chunk c+3
        if (c + 3 < nchunks) issue_chunk(c + 3);
        cp_commit();           // always commit (group may be empty)

        // ---- MMA phase: 4 k-steps x 4 expert-pairs x 3 products ----
        #pragma unroll
        for (int ks = 0; ks < 4; ks++) {
            const uint32_t kb = (uint32_t)(ks * 32);
            uint32_t ah0, ah1, ah2, ah3, al0, al1, al2, al3;
            ldm_x4(sbase + SM_XH + aoff + kb, ah0, ah1, ah2, ah3);
            ldm_x4(sbase + SM_XL + aoff + kb, al0, al1, al2, al3);
            #pragma unroll
            for (int p = 0; p < 4; p++) {
                const uint32_t bo = boff_base + (uint32_t)(p * 16 * (RS * 2)) + kb;
                uint32_t bh0, bh1, bh2, bh3, bl0, bl1, bl2, bl3;
                ldm_x4(sbase + SM_WH + bo, bh0, bh1, bh2, bh3);
                ldm_x4(sbase + SM_WL + bo, bl0, bl1, bl2, bl3);
                mma_bf16(acc[2 * p], ah0, ah1, ah2, ah3, bh0, bh1);
                mma_bf16(acc[2 * p], ah0, ah1, ah2, ah3, bl0, bl1);
                mma_bf16(acc[2 * p], al0, al1, al2, al3, bh0, bh1);
                mma_bf16(acc[2 * p + 1], ah0, ah1, ah2, ah3, bh2, bh3);
                mma_bf16(acc[2 * p + 1], ah0, ah1, ah2, ah3, bl2, bl3);
                mma_bf16(acc[2 * p + 1], al0, al1, al2, al3, bh2, bh3);
            }
        }
    }

    __syncthreads();

    // ---- write accumulators to padded smem scores [128][SSTR] ----
    float* scores = reinterpret_cast<float*>(dyn);
    {
        const int g  = lane >> 2;
        const int t2 = (lane & 3) * 2;
        #pragma unroll
        for (int n = 0; n < 8; n++) {
            const int col = n * 8 + t2;
            scores[(tokb + g) * SSTR + col]         = acc[n][0];
            scores[(tokb + g) * SSTR + col + 1]     = acc[n][1];
            scores[(tokb + g + 8) * SSTR + col]     = acc[n][2];
            scores[(tokb + g + 8) * SSTR + col + 1] = acc[n][3];
        }
    }
    __syncthreads();

    // ---- fast epilogue: 1 thread per token, all state in smem ----
    if (tid < TB) {
        float* srow = scores + tid * SSTR;
        float m = -FLT_MAX;
        #pragma unroll
        for (int e = 0; e < NE; e++) m = fmaxf(m, srow[e]);

        float denom = 0.0f;
        #pragma unroll
        for (int e = 0; e < NE; e++) {
            float q = __expf(srow[e] - m);
            if (q < FLT_MIN) q = 0.0f;
            denom += q;
        }

        bool flag = false;
        float b2 = LN_FLT_MIN + __logf(denom);
        #pragma unroll
        for (int e = 0; e < NE; e++) {
            float d = srow[e] - m;
            if (fabsf(d - LN_FLT_MIN) < EPS_B || fabsf(d - b2) < EPS_B) flag = true;
        }
        {
            unsigned long long used = 0ull;
            float prevv = 0.0f;
            for (int j = 0; j < 9; j++) {
                float best = -FLT_MAX; int bi = 0;
                for (int e = 0; e < NE; e++)
                    if (!((used >> e) & 1ull) && srow[e] > best) { best = srow[e]; bi = e; }
                used |= 1ull << bi;
                if (j > 0 && (prevv - best) < EPS_GAP) flag = true;
                prevv = best;
            }
        }

        float inv = 1.0f / denom;
        #pragma unroll
        for (int e = 0; e < NE; e++) {
            float q = __expf(srow[e] - m);
            if (q < FLT_MIN) q = 0.0f;
            q *= inv;
            if (q < FLT_MIN) q = 0.0f;
            srow[e] = q;
        }

        const int tglob = token0 + tid;
        float* out_w   = out + (size_t)tglob * TOPK;
        float* out_idx = out + (size_t)tokens * TOPK + (size_t)tglob * TOPK;
        #pragma unroll
        for (int j = 0; j < TOPK; j++) {
            float best = -1.0f; int bi = 0;
            for (int e = 0; e < NE; e++)
                if (srow[e] > best) { best = srow[e]; bi = e; }
            srow[bi] = -1.0f;
            out_w[j]   = best;
            out_idx[j] = (float)bi;
        }

        if (flag) {
            int i = atomicAdd(&s_nflag, 1);
            if (i < MAXFLAG) s_flags[i] = tid;
        }
    }
    __syncthreads();

    // ---- in-CTA exact fixup (serial fp32, split-K4 fold) ----
    const int nf = (s_nflag < MAXFLAG) ? s_nflag : MAXFLAG;
    if (nf > 0) {
        const int e  = tid & 63;
        const int sl = tid >> 6;            // slice 0..3
        const int slice = dim >> 2;         // 1024
        float* fixb = reinterpret_cast<float*>(dyn + SM_FIX);

        for (int f0 = 0; f0 < nf; f0 += 2) {
            const int f1 = (f0 + 1 < nf) ? f0 + 1 : f0;
            const float* xr0 = x + (size_t)(token0 + s_flags[f0]) * dim + sl * slice;
            const float* xr1 = x + (size_t)(token0 + s_flags[f1]) * dim + sl * slice;
            const float* wrp = w + (size_t)e * dim + sl * slice;
            float a0 = 0.0f, a1 = 0.0f;
            for (int k = 0; k < slice; k += 4) {
                float4 wv = *reinterpret_cast<const float4*>(wrp + k);
                float4 v0 = *reinterpret_cast<const float4*>(xr0 + k);
                float4 v1 = *reinterpret_cast<const float4*>(xr1 + k);
                a0 = fmaf(v0.x, wv.x, a0); a1 = fmaf(v1.x, wv.x, a1);
                a0 = fmaf(v0.y, wv.y, a0); a1 = fmaf(v1.y, wv.y, a1);
                a0 = fmaf(v0.z, wv.z, a0); a1 = fmaf(v1.z, wv.z, a1);
                a0 = fmaf(v0.w, wv.w, a0); a1 = fmaf(v1.w, wv.w, a1);
            }
            s_part[0][e * 4 + sl] = a0;
            s_part[1][e * 4 + sl] = a1;
            __syncthreads();
            if (tid < NE) {
                float t0 = ((s_part[0][tid * 4] + s_part[0][tid * 4 + 1])
                            + s_part[0][tid * 4 + 2]) + s_part[0][tid * 4 + 3];
                float t1 = ((s_part[1][tid * 4] + s_part[1][tid * 4 + 1])
                            + s_part[1][tid * 4 + 2]) + s_part[1][tid * 4 + 3];
                fixb[f0 * FSTR + tid] = t0;
                fixb[f1 * FSTR + tid] = t1;
            }
            __syncthreads();
        }

        if (tid < nf) {
            float* srow = fixb + tid * FSTR;
            float m = -FLT_MAX;
            for (int ee = 0; ee < NE; ee++) m = fmaxf(m, srow[ee]);
            float denom = 0.0f;
            for (int ee = 0; ee < NE; ee++) {
                float q = expf(srow[ee] - m);
                if (q < FLT_MIN) q = 0.0f;
                srow[ee] = q;
                denom += q;
            }
            float inv = 1.0f / denom;
            for (int ee = 0; ee < NE; ee++) {
                float q = srow[ee] * inv;
                if (q < FLT_MIN) q = 0.0f;
                srow[ee] = q;
            }
            const int tglob = token0 + s_flags[tid];
            float* out_w   = out + (size_t)tglob * TOPK;
            float* out_idx = out + (size_t)tokens * TOPK + (size_t)tglob * TOPK;
            for (int j = 0; j < TOPK; j++) {
                float best = -1.0f; int bi = 0;
                for (int ee = 0; ee < NE; ee++)
                    if (srow[ee] > best) { best = srow[ee]; bi = ee; }
                srow[bi] = -1.0f;
                out_w[j]   = best;
                out_idx[j] = (float)bi;
            }
        }
    }
}

// ================= launch =================
extern "C" void kernel_launch(void* const* d_in, const int* in_sizes, int n_in,
                              void* d_out, int out_size)
{
    const float* x = (const float*)d_in[0];
    const float* w = (const float*)d_in[1];
    // d_in[2] = bias: dead code in the reference

    const int num_experts = in_sizes[2];                 // 64
    const int dim         = in_sizes[1] / num_experts;   // 4096
    const int tokens      = in_sizes[0] / dim;           // 16384
    float* out = (float*)d_out;

    // idempotent, called every time (no static guards allowed)
    cudaFuncSetAttribute(gate_kernel,
                         cudaFuncAttributeMaxDynamicSharedMemorySize, SMEM_DYN);

    gate_kernel<<<tokens / TB, NT, SMEM_DYN>>>(x, w, out, dim, tokens);
}